// round 5
// baseline (speedup 1.0000x reference)
#include <cuda_runtime.h>
#include <math.h>

#define Bn 16
#define Ln 2048
#define Dn 512
#define En 8
#define Hn 8
#define HDn 64
#define EHn 64
#define Fn 2048

typedef unsigned long long ull;

// -------- scratch --------
__device__ float g_gates[Bn*En];
__device__ float g_xn[Bn*Dn];
__device__ float g_qhp[4*En*Bn*Dn];        // k1 partials (split over reduction d)
__device__ float g_qk[Bn*EHn*Dn];
__device__ float g_scores[Bn*EHn*Ln];      // 8 MB, becomes probs in place
__device__ float g_ent[Bn*En];
__device__ float g_prp[4*Bn*EHn*Dn];       // k5 partials (split over L)
__device__ float g_attnp[4*En*Bn*Dn];      // k6a partials
__device__ float g_xp[4*En*Bn*Dn];         // k6b partials
__device__ float g_x[Bn*En*Dn];
__device__ float g_xo[Bn*En*Dn];
__device__ float g_h[Bn*En*Fn];
__device__ float g_y4[4*Bn*En*Dn];         // FFN2 f-split partials

__device__ __forceinline__ void fma2(ull &c, ull a, ull b) {
    asm("fma.rn.f32x2 %0, %1, %2, %0;" : "+l"(c) : "l"(a), "l"(b));
}

// K0: gating softmax + normalized query xn. grid=B, block=256
__global__ void k0_gate_ln(const float* __restrict__ query, const float* __restrict__ w_gate) {
    int b = blockIdx.x, t = threadIdx.x;
    __shared__ float q[Dn];
    __shared__ float red[256];
    __shared__ float lred[256*8];
    q[t] = query[b*Dn + t];
    q[t+256] = query[b*Dn + t + 256];
    __syncthreads();
    red[t] = q[t] + q[t+256];
    __syncthreads();
    for (int o = 128; o; o >>= 1) { if (t < o) red[t] += red[t+o]; __syncthreads(); }
    float mu = red[0] * (1.0f/Dn);
    __syncthreads();
    float d0 = q[t] - mu, d1 = q[t+256] - mu;
    red[t] = d0*d0 + d1*d1;
    __syncthreads();
    for (int o = 128; o; o >>= 1) { if (t < o) red[t] += red[t+o]; __syncthreads(); }
    float rstd = rsqrtf(red[0] * (1.0f/Dn) + 1e-5f);
    #pragma unroll
    for (int e = 0; e < 8; e++)
        lred[t*8+e] = q[t]*w_gate[t*8+e] + q[t+256]*w_gate[(t+256)*8+e];
    __syncthreads();
    for (int o = 128; o; o >>= 1) {
        if (t < o) {
            #pragma unroll
            for (int e = 0; e < 8; e++) lred[t*8+e] += lred[(t+o)*8+e];
        }
        __syncthreads();
    }
    if (t == 0) {
        float m = -1e30f;
        for (int e = 0; e < 8; e++) m = fmaxf(m, lred[e]);
        float s = 0.0f, ex[8];
        for (int e = 0; e < 8; e++) { ex[e] = expf(lred[e]-m); s += ex[e]; }
        for (int e = 0; e < 8; e++) g_gates[b*8+e] = ex[e]/s;
    }
    g_xn[b*Dn + t]       = d0*rstd;
    g_xn[b*Dn + t + 256] = d1*rstd;
}

// K1: qh partials, 2 outputs/thread. grid=(4 ktiles, E, 4 dsplit), block=256 (4 g x 64 lanes)
__global__ void __launch_bounds__(256) k1_qh(const float* __restrict__ ln_q_g,
                      const float* __restrict__ ln_q_b,
                      const float* __restrict__ Wq) {
    int e = blockIdx.y, k0 = blockIdx.x*128, s = blockIdx.z;
    int t = threadIdx.x, g = t >> 6, lane = t & 63;
    __shared__ float qn[Bn*128];
    __shared__ float red[4*Bn*128];
    for (int i = t; i < Bn*128; i += 256) {
        int b = i >> 7, dd = i & 127;
        int d = s*128 + dd;
        qn[b*128+dd] = g_xn[b*Dn+d]*ln_q_g[e*Dn+d] + ln_q_b[e*Dn+d];
    }
    __syncthreads();
    float acc0[Bn], acc1[Bn];
    #pragma unroll
    for (int b = 0; b < Bn; b++) { acc0[b] = 0.0f; acc1[b] = 0.0f; }
    const float* W = Wq + (size_t)e*Dn*Dn + (size_t)(s*128 + g*32)*Dn + k0 + lane;
    #pragma unroll
    for (int d = 0; d < 32; d += 8) {
        float w0[8], w1[8];
        #pragma unroll
        for (int j = 0; j < 8; j++) {
            w0[j] = W[(size_t)(d+j)*Dn];
            w1[j] = W[(size_t)(d+j)*Dn + 64];
        }
        #pragma unroll
        for (int b = 0; b < Bn; b++) {
            float4 p0 = *(const float4*)&qn[b*128 + g*32 + d];
            float4 p1 = *(const float4*)&qn[b*128 + g*32 + d + 4];
            acc0[b] = fmaf(p0.x, w0[0], acc0[b]); acc1[b] = fmaf(p0.x, w1[0], acc1[b]);
            acc0[b] = fmaf(p0.y, w0[1], acc0[b]); acc1[b] = fmaf(p0.y, w1[1], acc1[b]);
            acc0[b] = fmaf(p0.z, w0[2], acc0[b]); acc1[b] = fmaf(p0.z, w1[2], acc1[b]);
            acc0[b] = fmaf(p0.w, w0[3], acc0[b]); acc1[b] = fmaf(p0.w, w1[3], acc1[b]);
            acc0[b] = fmaf(p1.x, w0[4], acc0[b]); acc1[b] = fmaf(p1.x, w1[4], acc1[b]);
            acc0[b] = fmaf(p1.y, w0[5], acc0[b]); acc1[b] = fmaf(p1.y, w1[5], acc1[b]);
            acc0[b] = fmaf(p1.z, w0[6], acc0[b]); acc1[b] = fmaf(p1.z, w1[6], acc1[b]);
            acc0[b] = fmaf(p1.w, w0[7], acc0[b]); acc1[b] = fmaf(p1.w, w1[7], acc1[b]);
        }
    }
    __syncthreads();
    #pragma unroll
    for (int b = 0; b < Bn; b++) {
        red[(g*Bn + b)*128 + lane]      = acc0[b];
        red[(g*Bn + b)*128 + lane + 64] = acc1[b];
    }
    __syncthreads();
    for (int i = t; i < Bn*128; i += 256) {
        int b = i >> 7, kk = i & 127;
        float v = red[(0*Bn+b)*128+kk]+red[(1*Bn+b)*128+kk]+red[(2*Bn+b)*128+kk]+red[(3*Bn+b)*128+kk];
        g_qhp[(((size_t)s*En + e)*Bn + b)*Dn + k0 + kk] = v;
    }
}

// K2: qk[b,eh,d] = (sum partials + bq) . Wk row slices, scaled. grid=(EH, 2), block=256
__global__ void __launch_bounds__(256) k2_qk(const float* __restrict__ Wk,
                                             const float* __restrict__ bq) {
    int eh = blockIdx.x, dc = blockIdx.y;
    int e = eh >> 3, h = eh & 7;
    int t = threadIdx.x;
    int d = dc*256 + t;
    __shared__ float qs[Bn][HDn];
    for (int i = t; i < Bn*HDn; i += 256) {
        int b = i >> 6, c = i & 63;
        float v = bq[e*Dn + h*HDn + c];
        #pragma unroll
        for (int s = 0; s < 4; s++)
            v += g_qhp[(((size_t)s*En + e)*Bn + b)*Dn + h*HDn + c];
        qs[b][c] = v;
    }
    __syncthreads();
    const float4* W4 = (const float4*)(Wk + (size_t)e*Dn*Dn + (size_t)d*Dn + h*HDn);
    float acc[Bn];
    #pragma unroll
    for (int b = 0; b < Bn; b++) acc[b] = 0.0f;
    #pragma unroll
    for (int c4 = 0; c4 < 16; c4++) {
        float4 w = W4[c4];
        int c = c4*4;
        #pragma unroll
        for (int b = 0; b < Bn; b++) {
            acc[b] = fmaf(qs[b][c],   w.x, acc[b]);
            acc[b] = fmaf(qs[b][c+1], w.y, acc[b]);
            acc[b] = fmaf(qs[b][c+2], w.z, acc[b]);
            acc[b] = fmaf(qs[b][c+3], w.w, acc[b]);
        }
    }
    #pragma unroll
    for (int b = 0; b < Bn; b++) g_qk[((size_t)b*EHn+eh)*Dn + d] = acc[b]*0.125f;
}

// K3: scores = R @ qk^T per b. Tile 128(l) x 64(eh), K=512, 128 threads, 8x8 micro f32x2.
__global__ void __launch_bounds__(128, 3) k3_scores(const float* __restrict__ R) {
    int b = blockIdx.y, l0 = blockIdx.x*128;
    int t = threadIdx.x, tx = t & 15, ty = t >> 4;
    __shared__ float As[2][16][132];
    __shared__ float2 Bd[2][16][66];
    ull acc[8][4];
    #pragma unroll
    for (int i = 0; i < 8; i++)
        #pragma unroll
        for (int j = 0; j < 4; j++) acc[i][j] = 0ull;

    int lw = t & 31, kq = t >> 5;
    int ehB = t >> 1, kb = (t & 1)*8;
    const float* Ar = R + ((size_t)b*Ln + l0 + lw*4)*Dn + kq*4;
    const float* Br = g_qk + ((size_t)b*EHn + ehB)*Dn + kb;

    float4 a0 = *(const float4*)(Ar + 0*Dn);
    float4 a1 = *(const float4*)(Ar + 1*Dn);
    float4 a2 = *(const float4*)(Ar + 2*Dn);
    float4 a3 = *(const float4*)(Ar + 3*Dn);
    float4 b0 = *(const float4*)(Br);
    float4 b1 = *(const float4*)(Br + 4);

    for (int s = 0; s < 32; s++) {
        int cur = s & 1;
        *(float4*)&As[cur][kq*4+0][lw*4] = make_float4(a0.x, a1.x, a2.x, a3.x);
        *(float4*)&As[cur][kq*4+1][lw*4] = make_float4(a0.y, a1.y, a2.y, a3.y);
        *(float4*)&As[cur][kq*4+2][lw*4] = make_float4(a0.z, a1.z, a2.z, a3.z);
        *(float4*)&As[cur][kq*4+3][lw*4] = make_float4(a0.w, a1.w, a2.w, a3.w);
        Bd[cur][kb+0][ehB] = make_float2(b0.x, b0.x);
        Bd[cur][kb+1][ehB] = make_float2(b0.y, b0.y);
        Bd[cur][kb+2][ehB] = make_float2(b0.z, b0.z);
        Bd[cur][kb+3][ehB] = make_float2(b0.w, b0.w);
        Bd[cur][kb+4][ehB] = make_float2(b1.x, b1.x);
        Bd[cur][kb+5][ehB] = make_float2(b1.y, b1.y);
        Bd[cur][kb+6][ehB] = make_float2(b1.z, b1.z);
        Bd[cur][kb+7][ehB] = make_float2(b1.w, b1.w);
        __syncthreads();
        if (s+1 < 32) {
            const float* An = Ar + (s+1)*16;
            a0 = *(const float4*)(An + 0*Dn);
            a1 = *(const float4*)(An + 1*Dn);
            a2 = *(const float4*)(An + 2*Dn);
            a3 = *(const float4*)(An + 3*Dn);
            const float* Bq = Br + (s+1)*16;
            b0 = *(const float4*)(Bq);
            b1 = *(const float4*)(Bq + 4);
        }
        #pragma unroll
        for (int kk = 0; kk < 16; kk++) {
            ulonglong2 A01 = *(const ulonglong2*)&As[cur][kk][tx*8];
            ulonglong2 A23 = *(const ulonglong2*)&As[cur][kk][tx*8+4];
            ulonglong2 B01 = *(const ulonglong2*)&Bd[cur][kk][ty*8];
            ulonglong2 B23 = *(const ulonglong2*)&Bd[cur][kk][ty*8+2];
            ulonglong2 B45 = *(const ulonglong2*)&Bd[cur][kk][ty*8+4];
            ulonglong2 B67 = *(const ulonglong2*)&Bd[cur][kk][ty*8+6];
            ull av[4] = {A01.x, A01.y, A23.x, A23.y};
            ull bv8[8] = {B01.x, B01.y, B23.x, B23.y, B45.x, B45.y, B67.x, B67.y};
            #pragma unroll
            for (int i = 0; i < 8; i++)
                #pragma unroll
                for (int j = 0; j < 4; j++) fma2(acc[i][j], bv8[i], av[j]);
        }
        __syncthreads();
    }
    #pragma unroll
    for (int i = 0; i < 8; i++) {
        int eh = ty*8 + i;
        float2* dst = (float2*)&g_scores[((size_t)b*EHn + eh)*Ln + l0 + tx*8];
        #pragma unroll
        for (int j = 0; j < 4; j++) dst[j] = *(float2*)&acc[i][j];
    }
}

// K4: softmax per (b,e,h) warp-per-head + entropy. grid=B*E, block=256
__global__ void __launch_bounds__(256) k4_softmax() {
    int be = blockIdx.x;
    int t = threadIdx.x, w = t >> 5, lane = t & 31;
    __shared__ float red[256];
    float* base = g_scores + (size_t)be*Hn*Ln;
    float* src = base + (size_t)w*Ln;
    float4 v[16];
    float m = -1e30f;
    #pragma unroll
    for (int i = 0; i < 16; i++) {
        v[i] = *(const float4*)&src[(i*32 + lane)*4];
        m = fmaxf(m, fmaxf(fmaxf(v[i].x, v[i].y), fmaxf(v[i].z, v[i].w)));
    }
    #pragma unroll
    for (int o = 16; o; o >>= 1) m = fmaxf(m, __shfl_xor_sync(0xffffffffu, m, o));
    float s = 0.0f;
    #pragma unroll
    for (int i = 0; i < 16; i++) {
        v[i].x = __expf(v[i].x - m); v[i].y = __expf(v[i].y - m);
        v[i].z = __expf(v[i].z - m); v[i].w = __expf(v[i].w - m);
        s += v[i].x + v[i].y + v[i].z + v[i].w;
    }
    #pragma unroll
    for (int o = 16; o; o >>= 1) s += __shfl_xor_sync(0xffffffffu, s, o);
    float inv = 1.0f/s;
    #pragma unroll
    for (int i = 0; i < 16; i++) {
        v[i].x *= inv; v[i].y *= inv; v[i].z *= inv; v[i].w *= inv;
        *(float4*)&src[(i*32 + lane)*4] = v[i];
    }
    __syncthreads();
    float lent = 0.0f;
    for (int i = t; i < Ln; i += 256) {
        float s8 = 0.0f;
        #pragma unroll
        for (int h = 0; h < 8; h++) s8 += base[h*Ln + i];
        float p = fmaxf(s8*0.125f, 1e-12f);
        lent -= p*__logf(p);
    }
    red[t] = lent; __syncthreads();
    for (int o = 128; o; o >>= 1) { if (t < o) red[t] += red[t+o]; __syncthreads(); }
    if (t == 0) g_ent[be] = red[0];
}

// K5: pr partial = probs-chunk @ R-chunk. Tile 64(eh) x 128(d), 128 threads, 8x8 micro.
__global__ void __launch_bounds__(128, 3) k5_pr(const float* __restrict__ R) {
    int b = blockIdx.y, d0 = blockIdx.x*128, ks = blockIdx.z;
    int t = threadIdx.x, tx = t & 15, ty = t >> 4;
    __shared__ float Bs[2][16][132];
    __shared__ float2 Ad[2][16][66];
    ull acc[8][4];
    #pragma unroll
    for (int i = 0; i < 8; i++)
        #pragma unroll
        for (int j = 0; j < 4; j++) acc[i][j] = 0ull;

    int ehA = t >> 1, ka = (t & 1)*8;
    int kkB = t >> 3, dsg = (t & 7)*16;
    const float* Pr = g_scores + ((size_t)b*EHn + ehA)*Ln + ks*512 + ka;
    const float* Rr = R + ((size_t)b*Ln + ks*512 + kkB)*Dn + d0 + dsg;

    float4 p0 = *(const float4*)(Pr);
    float4 p1 = *(const float4*)(Pr + 4);
    float4 r0 = *(const float4*)(Rr + 0);
    float4 r1 = *(const float4*)(Rr + 4);
    float4 r2 = *(const float4*)(Rr + 8);
    float4 r3 = *(const float4*)(Rr + 12);

    for (int s = 0; s < 32; s++) {
        int cur = s & 1;
        Ad[cur][ka+0][ehA] = make_float2(p0.x, p0.x);
        Ad[cur][ka+1][ehA] = make_float2(p0.y, p0.y);
        Ad[cur][ka+2][ehA] = make_float2(p0.z, p0.z);
        Ad[cur][ka+3][ehA] = make_float2(p0.w, p0.w);
        Ad[cur][ka+4][ehA] = make_float2(p1.x, p1.x);
        Ad[cur][ka+5][ehA] = make_float2(p1.y, p1.y);
        Ad[cur][ka+6][ehA] = make_float2(p1.z, p1.z);
        Ad[cur][ka+7][ehA] = make_float2(p1.w, p1.w);
        *(float4*)&Bs[cur][kkB][dsg+0]  = r0;
        *(float4*)&Bs[cur][kkB][dsg+4]  = r1;
        *(float4*)&Bs[cur][kkB][dsg+8]  = r2;
        *(float4*)&Bs[cur][kkB][dsg+12] = r3;
        __syncthreads();
        if (s+1 < 32) {
            const float* Pn = Pr + (s+1)*16;
            p0 = *(const float4*)(Pn);
            p1 = *(const float4*)(Pn + 4);
            const float* Rn = Rr + (size_t)(s+1)*16*Dn;
            r0 = *(const float4*)(Rn + 0);
            r1 = *(const float4*)(Rn + 4);
            r2 = *(const float4*)(Rn + 8);
            r3 = *(const float4*)(Rn + 12);
        }
        #pragma unroll
        for (int kk = 0; kk < 16; kk++) {
            ulonglong2 B01 = *(const ulonglong2*)&Bs[cur][kk][tx*8];
            ulonglong2 B23 = *(const ulonglong2*)&Bs[cur][kk][tx*8+4];
            ulonglong2 A01 = *(const ulonglong2*)&Ad[cur][kk][ty*8];
            ulonglong2 A23 = *(const ulonglong2*)&Ad[cur][kk][ty*8+2];
            ulonglong2 A45 = *(const ulonglong2*)&Ad[cur][kk][ty*8+4];
            ulonglong2 A67 = *(const ulonglong2*)&Ad[cur][kk][ty*8+6];
            ull bvv[4] = {B01.x, B01.y, B23.x, B23.y};
            ull avv[8] = {A01.x, A01.y, A23.x, A23.y, A45.x, A45.y, A67.x, A67.y};
            #pragma unroll
            for (int i = 0; i < 8; i++)
                #pragma unroll
                for (int j = 0; j < 4; j++) fma2(acc[i][j], avv[i], bvv[j]);
        }
        __syncthreads();
    }
    #pragma unroll
    for (int i = 0; i < 8; i++) {
        int eh = ty*8 + i;
        float2* dst = (float2*)&g_prp[(((size_t)ks*Bn + b)*EHn + eh)*Dn + d0 + tx*8];
        #pragma unroll
        for (int j = 0; j < 4; j++) dst[j] = *(float2*)&acc[i][j];
    }
}

// K6a: attn partials = pr @ Wv (split over d). 2 outputs/thread, 8 dgroups.
// grid=(EH, 4 s), block=256 (8 g x 32 lanes)
__global__ void __launch_bounds__(256) k6a_attn(const float* __restrict__ Wv) {
    int eh = blockIdx.x, s = blockIdx.y;
    int e = eh >> 3, h = eh & 7;
    int t = threadIdx.x, g = t >> 5, lane = t & 31;
    __shared__ float ps[Bn*128];
    __shared__ float sred[8*Bn*64];
    for (int i = t; i < Bn*128; i += 256) {
        int b = i >> 7, dd = i & 127;
        float v = 0.0f;
        #pragma unroll
        for (int ks = 0; ks < 4; ks++)
            v += g_prp[(((size_t)ks*Bn + b)*EHn + eh)*Dn + s*128 + dd];
        ps[b*128+dd] = v;
    }
    __syncthreads();
    float acc0[Bn], acc1[Bn];
    #pragma unroll
    for (int b = 0; b < Bn; b++) { acc0[b] = 0.0f; acc1[b] = 0.0f; }
    const float* W = Wv + (size_t)e*Dn*Dn + (size_t)(s*128 + g*16)*Dn + h*HDn + lane;
    #pragma unroll
    for (int d = 0; d < 16; d += 8) {
        float w0[8], w1[8];
        #pragma unroll
        for (int j = 0; j < 8; j++) {
            w0[j] = W[(size_t)(d+j)*Dn];
            w1[j] = W[(size_t)(d+j)*Dn + 32];
        }
        #pragma unroll
        for (int b = 0; b < Bn; b++) {
            float4 q0 = *(const float4*)&ps[b*128 + g*16 + d];
            float4 q1 = *(const float4*)&ps[b*128 + g*16 + d + 4];
            acc0[b] = fmaf(q0.x, w0[0], acc0[b]); acc1[b] = fmaf(q0.x, w1[0], acc1[b]);
            acc0[b] = fmaf(q0.y, w0[1], acc0[b]); acc1[b] = fmaf(q0.y, w1[1], acc1[b]);
            acc0[b] = fmaf(q0.z, w0[2], acc0[b]); acc1[b] = fmaf(q0.z, w1[2], acc1[b]);
            acc0[b] = fmaf(q0.w, w0[3], acc0[b]); acc1[b] = fmaf(q0.w, w1[3], acc1[b]);
            acc0[b] = fmaf(q1.x, w0[4], acc0[b]); acc1[b] = fmaf(q1.x, w1[4], acc1[b]);
            acc0[b] = fmaf(q1.y, w0[5], acc0[b]); acc1[b] = fmaf(q1.y, w1[5], acc1[b]);
            acc0[b] = fmaf(q1.z, w0[6], acc0[b]); acc1[b] = fmaf(q1.z, w1[6], acc1[b]);
            acc0[b] = fmaf(q1.w, w0[7], acc0[b]); acc1[b] = fmaf(q1.w, w1[7], acc1[b]);
        }
    }
    __syncthreads();
    #pragma unroll
    for (int b = 0; b < Bn; b++) {
        sred[(g*Bn + b)*64 + lane]      = acc0[b];
        sred[(g*Bn + b)*64 + lane + 32] = acc1[b];
    }
    __syncthreads();
    for (int i = t; i < Bn*64; i += 256) {
        int b = i >> 6, cc = i & 63;
        float v = 0.0f;
        #pragma unroll
        for (int gg = 0; gg < 8; gg++) v += sred[(gg*Bn + b)*64 + cc];
        g_attnp[(((size_t)s*En + e)*Bn + b)*Dn + h*HDn + cc] = v;
    }
}

// K6b: x partials = attn @ Wo (split over d). 2 outputs/thread.
// grid=(4 ktiles, E, 4 s), block=256 (4 g x 64 lanes)
__global__ void __launch_bounds__(256) k6b_attnout(const float* __restrict__ Wo,
                                                   const float* __restrict__ bv) {
    int e = blockIdx.y, k0 = blockIdx.x*128, s = blockIdx.z;
    int t = threadIdx.x, g = t >> 6, lane = t & 63;
    __shared__ float as_[Bn*128];
    __shared__ float red[4*Bn*128];
    for (int i = t; i < Bn*128; i += 256) {
        int b = i >> 7, dd = i & 127;
        int d = s*128 + dd;
        float v = bv[e*Dn + d];
        #pragma unroll
        for (int sp = 0; sp < 4; sp++)
            v += g_attnp[(((size_t)sp*En + e)*Bn + b)*Dn + d];
        as_[b*128+dd] = v;
    }
    __syncthreads();
    float acc0[Bn], acc1[Bn];
    #pragma unroll
    for (int b = 0; b < Bn; b++) { acc0[b] = 0.0f; acc1[b] = 0.0f; }
    const float* W = Wo + (size_t)e*Dn*Dn + (size_t)(s*128 + g*32)*Dn + k0 + lane;
    #pragma unroll
    for (int d = 0; d < 32; d += 8) {
        float w0[8], w1[8];
        #pragma unroll
        for (int j = 0; j < 8; j++) {
            w0[j] = W[(size_t)(d+j)*Dn];
            w1[j] = W[(size_t)(d+j)*Dn + 64];
        }
        #pragma unroll
        for (int b = 0; b < Bn; b++) {
            float4 q0 = *(const float4*)&as_[b*128 + g*32 + d];
            float4 q1 = *(const float4*)&as_[b*128 + g*32 + d + 4];
            acc0[b] = fmaf(q0.x, w0[0], acc0[b]); acc1[b] = fmaf(q0.x, w1[0], acc1[b]);
            acc0[b] = fmaf(q0.y, w0[1], acc0[b]); acc1[b] = fmaf(q0.y, w1[1], acc1[b]);
            acc0[b] = fmaf(q0.z, w0[2], acc0[b]); acc1[b] = fmaf(q0.z, w1[2], acc1[b]);
            acc0[b] = fmaf(q0.w, w0[3], acc0[b]); acc1[b] = fmaf(q0.w, w1[3], acc1[b]);
            acc0[b] = fmaf(q1.x, w0[4], acc0[b]); acc1[b] = fmaf(q1.x, w1[4], acc1[b]);
            acc0[b] = fmaf(q1.y, w0[5], acc0[b]); acc1[b] = fmaf(q1.y, w1[5], acc1[b]);
            acc0[b] = fmaf(q1.z, w0[6], acc0[b]); acc1[b] = fmaf(q1.z, w1[6], acc1[b]);
            acc0[b] = fmaf(q1.w, w0[7], acc0[b]); acc1[b] = fmaf(q1.w, w1[7], acc1[b]);
        }
    }
    __syncthreads();
    #pragma unroll
    for (int b = 0; b < Bn; b++) {
        red[(g*Bn + b)*128 + lane]      = acc0[b];
        red[(g*Bn + b)*128 + lane + 64] = acc1[b];
    }
    __syncthreads();
    for (int i = t; i < Bn*128; i += 256) {
        int b = i >> 7, kk = i & 127;
        float v = red[(0*Bn+b)*128+kk]+red[(1*Bn+b)*128+kk]+red[(2*Bn+b)*128+kk]+red[(3*Bn+b)*128+kk];
        g_xp[(((size_t)s*En + e)*Bn + b)*Dn + k0 + kk] = v;
    }
}

// K_ln2: x = query + bo + sum xp; write g_x and g_xo=LN(x). grid=B*E, block=256
__global__ void __launch_bounds__(256) k_ln2(const float* __restrict__ ln_o_g,
                      const float* __restrict__ ln_o_b,
                      const float* __restrict__ bo, const float* __restrict__ query) {
    int be = blockIdx.x, b = be >> 3, e = be & 7;
    int t = threadIdx.x;
    __shared__ float red[256];
    float v0 = query[b*Dn + t]     + bo[e*Dn + t];
    float v1 = query[b*Dn + t+256] + bo[e*Dn + t+256];
    #pragma unroll
    for (int s = 0; s < 4; s++) {
        v0 += g_xp[(((size_t)s*En + e)*Bn + b)*Dn + t];
        v1 += g_xp[(((size_t)s*En + e)*Bn + b)*Dn + t + 256];
    }
    g_x[be*Dn + t] = v0;
    g_x[be*Dn + t+256] = v1;
    red[t] = v0 + v1; __syncthreads();
    for (int o = 128; o; o >>= 1) { if (t < o) red[t] += red[t+o]; __syncthreads(); }
    float mu = red[0]*(1.0f/Dn); __syncthreads();
    float d0 = v0-mu, d1 = v1-mu;
    red[t] = d0*d0 + d1*d1; __syncthreads();
    for (int o = 128; o; o >>= 1) { if (t < o) red[t] += red[t+o]; __syncthreads(); }
    float rstd = rsqrtf(red[0]*(1.0f/Dn) + 1e-5f);
    g_xo[be*Dn + t]     = d0*rstd*ln_o_g[e*Dn+t]     + ln_o_b[e*Dn+t];
    g_xo[be*Dn + t+256] = d1*rstd*ln_o_g[e*Dn+t+256] + ln_o_b[e*Dn+t+256];
}

// K7: h = gelu(xo @ W1 + b1). 2 outputs/thread. grid=(16 ftiles, E), block=256 (4 g x 64)
__global__ void __launch_bounds__(256) k7_ffn1(const float* __restrict__ W1,
                                               const float* __restrict__ b1) {
    int e = blockIdx.y, f0 = blockIdx.x*128;
    int t = threadIdx.x, g = t >> 6, lane = t & 63;
    __shared__ float xs[Bn*Dn];   // 32KB; reused as reduce buffer
    for (int i = t; i < Bn*Dn; i += 256) {
        int b = i >> 9, d = i & 511;
        xs[b*Dn+d] = g_xo[(b*En+e)*Dn + d];
    }
    __syncthreads();
    float acc0[Bn], acc1[Bn];
    #pragma unroll
    for (int b = 0; b < Bn; b++) { acc0[b] = 0.0f; acc1[b] = 0.0f; }
    const float* W = W1 + (size_t)e*Dn*Fn + (size_t)(g*128)*Fn + f0 + lane;
    #pragma unroll 2
    for (int d = 0; d < 128; d += 8) {
        float w0[8], w1[8];
        #pragma unroll
        for (int j = 0; j < 8; j++) {
            w0[j] = W[(size_t)(d+j)*Fn];
            w1[j] = W[(size_t)(d+j)*Fn + 64];
        }
        #pragma unroll
        for (int b = 0; b < Bn; b++) {
            float4 x0 = *(const float4*)&xs[b*Dn + g*128 + d];
            float4 x1 = *(const float4*)&xs[b*Dn + g*128 + d + 4];
            acc0[b] = fmaf(x0.x, w0[0], acc0[b]); acc1[b] = fmaf(x0.x, w1[0], acc1[b]);
            acc0[b] = fmaf(x0.y, w0[1], acc0[b]); acc1[b] = fmaf(x0.y, w1[1], acc1[b]);
            acc0[b] = fmaf(x0.z, w0[2], acc0[b]); acc1[b] = fmaf(x0.z, w1[2], acc1[b]);
            acc0[b] = fmaf(x0.w, w0[3], acc0[b]); acc1[b] = fmaf(x0.w, w1[3], acc1[b]);
            acc0[b] = fmaf(x1.x, w0[4], acc0[b]); acc1[b] = fmaf(x1.x, w1[4], acc1[b]);
            acc0[b] = fmaf(x1.y, w0[5], acc0[b]); acc1[b] = fmaf(x1.y, w1[5], acc1[b]);
            acc0[b] = fmaf(x1.z, w0[6], acc0[b]); acc1[b] = fmaf(x1.z, w1[6], acc1[b]);
            acc0[b] = fmaf(x1.w, w0[7], acc0[b]); acc1[b] = fmaf(x1.w, w1[7], acc1[b]);
        }
    }
    __syncthreads();
    float* red = xs;   // reuse (4*16*128 = 8192 floats)
    #pragma unroll
    for (int b = 0; b < Bn; b++) {
        red[(g*Bn + b)*128 + lane]      = acc0[b];
        red[(g*Bn + b)*128 + lane + 64] = acc1[b];
    }
    __syncthreads();
    for (int i = t; i < Bn*128; i += 256) {
        int b = i >> 7, ff = i & 127;
        float v = red[(0*Bn+b)*128+ff]+red[(1*Bn+b)*128+ff]+red[(2*Bn+b)*128+ff]+red[(3*Bn+b)*128+ff]
                + b1[e*Fn + f0+ff];
        v = 0.5f*v*(1.0f + erff(v*0.70710678118654752f));
        g_h[(b*En+e)*Fn + f0+ff] = v;
    }
}

// K8: y partials = h_chunk @ W2_chunk. 2 outputs/thread. grid=(4 ktiles, E, 4 fc), block=256
__global__ void __launch_bounds__(256) k8_ffn2(const float* __restrict__ W2) {
    int e = blockIdx.y, k0 = blockIdx.x*128, fc = blockIdx.z;
    int t = threadIdx.x, g = t >> 6, lane = t & 63;
    __shared__ float hs[Bn*512];   // 32KB; reused as reduce buffer
    for (int i = t; i < Bn*512; i += 256) {
        int b = i >> 9, f = i & 511;
        hs[b*512+f] = g_h[(b*En+e)*Fn + fc*512 + f];
    }
    __syncthreads();
    float acc0[Bn], acc1[Bn];
    #pragma unroll
    for (int b = 0; b < Bn; b++) { acc0[b] = 0.0f; acc1[b] = 0.0f; }
    const float* W = W2 + (size_t)e*Fn*Dn + ((size_t)fc*512 + g*128)*Dn + k0 + lane;
    #pragma unroll 2
    for (int ff = 0; ff < 128; ff += 8) {
        float w0[8], w1[8];
        #pragma unroll
        for (int j = 0; j < 8; j++) {
            w0[j] = W[(size_t)(ff+j)*Dn];
            w1[j] = W[(size_t)(ff+j)*Dn + 64];
        }
        #pragma unroll
        for (int b = 0; b < Bn; b++) {
            float4 h0 = *(const float4*)&hs[b*512 + g*128 + ff];
            float4 h1 = *(const float4*)&hs[b*512 + g*128 + ff + 4];
            acc0[b] = fmaf(h0.x, w0[0], acc0[b]); acc1[b] = fmaf(h0.x, w1[0], acc1[b]);
            acc0[b] = fmaf(h0.y, w0[1], acc0[b]); acc1[b] = fmaf(h0.y, w1[1], acc1[b]);
            acc0[b] = fmaf(h0.z, w0[2], acc0[b]); acc1[b] = fmaf(h0.z, w1[2], acc1[b]);
            acc0[b] = fmaf(h0.w, w0[3], acc0[b]); acc1[b] = fmaf(h0.w, w1[3], acc1[b]);
            acc0[b] = fmaf(h1.x, w0[4], acc0[b]); acc1[b] = fmaf(h1.x, w1[4], acc1[b]);
            acc0[b] = fmaf(h1.y, w0[5], acc0[b]); acc1[b] = fmaf(h1.y, w1[5], acc1[b]);
            acc0[b] = fmaf(h1.z, w0[6], acc0[b]); acc1[b] = fmaf(h1.z, w1[6], acc1[b]);
            acc0[b] = fmaf(h1.w, w0[7], acc0[b]); acc1[b] = fmaf(h1.w, w1[7], acc1[b]);
        }
    }
    __syncthreads();
    float* red = hs;   // reuse
    #pragma unroll
    for (int b = 0; b < Bn; b++) {
        red[(g*Bn + b)*128 + lane]      = acc0[b];
        red[(g*Bn + b)*128 + lane + 64] = acc1[b];
    }
    __syncthreads();
    for (int i = t; i < Bn*128; i += 256) {
        int b = i >> 7, kk = i & 127;
        float v = red[(0*Bn+b)*128+kk]+red[(1*Bn+b)*128+kk]+red[(2*Bn+b)*128+kk]+red[(3*Bn+b)*128+kk];
        g_y4[(((size_t)fc*Bn + b)*En + e)*Dn + k0 + kk] = v;
    }
}

// K9: assemble y = x + b2 + sum partials; weights; mixture. grid=B, block=512
__global__ void __launch_bounds__(512) k9_final(float* __restrict__ out,
                                                const float* __restrict__ b2) {
    int b = blockIdx.x, t = threadIdx.x;
    __shared__ float gt[8];
    if (t < 8) gt[t] = g_gates[b*8+t]*__expf(-0.5f*g_ent[b*8+t]);
    __syncthreads();
    if (t == 0) {
        float s = 0.0f;
        for (int e = 0; e < 8; e++) s += gt[e];
        float inv = 1.0f/(s + 1e-9f);
        for (int e = 0; e < 8; e++) gt[e] *= inv;
    }
    __syncthreads();
    if (t < 8) out[Bn*Dn + Bn*En*Dn + b*8 + t] = gt[t];
    float m = 0.0f;
    #pragma unroll
    for (int e = 0; e < 8; e++) {
        float y = g_x[(b*En+e)*Dn + t] + b2[e*Dn + t];
        #pragma unroll
        for (int fc = 0; fc < 4; fc++)
            y += g_y4[(((size_t)fc*Bn + b)*En + e)*Dn + t];
        out[Bn*Dn + (b*En+e)*Dn + t] = y;
        m = fmaf(gt[e], y, m);
    }
    out[b*Dn + t] = m;   // ALPHA=1 -> fused = mixture
}

extern "C" void kernel_launch(void* const* d_in, const int* in_sizes, int n_in,
                              void* d_out, int out_size) {
    const float* query     = (const float*)d_in[0];
    const float* retrieved = (const float*)d_in[1];
    const float* w_gate    = (const float*)d_in[2];
    const float* ln_q_g    = (const float*)d_in[3];
    const float* ln_q_b    = (const float*)d_in[4];
    const float* Wq        = (const float*)d_in[5];
    const float* bq        = (const float*)d_in[6];
    const float* Wk        = (const float*)d_in[7];
    /* d_in[8] = bk cancels in softmax */
    const float* Wv        = (const float*)d_in[9];
    const float* bv        = (const float*)d_in[10];
    const float* Wo        = (const float*)d_in[11];
    const float* bo        = (const float*)d_in[12];
    const float* ln_o_g    = (const float*)d_in[13];
    const float* ln_o_b    = (const float*)d_in[14];
    const float* W1        = (const float*)d_in[15];
    const float* b1        = (const float*)d_in[16];
    const float* W2        = (const float*)d_in[17];
    const float* b2        = (const float*)d_in[18];
    float* out = (float*)d_out;

    k0_gate_ln<<<Bn, 256>>>(query, w_gate);
    k1_qh<<<dim3(4, En, 4), 256>>>(ln_q_g, ln_q_b, Wq);
    k2_qk<<<dim3(EHn, 2), 256>>>(Wk, bq);
    k3_scores<<<dim3(16, Bn), 128>>>(retrieved);
    k4_softmax<<<Bn*En, 256>>>();
    k5_pr<<<dim3(4, Bn, 4), 128>>>(retrieved);
    k6a_attn<<<dim3(EHn, 4), 256>>>(Wv);
    k6b_attnout<<<dim3(4, En, 4), 256>>>(Wo, bv);
    k_ln2<<<Bn*En, 256>>>(ln_o_g, ln_o_b, bo, query);
    k7_ffn1<<<dim3(16, En), 256>>>(W1, b1);
    k8_ffn2<<<dim3(4, En, 4), 256>>>(W2);
    k9_final<<<Bn, 512>>>(out, b2);
}

// round 6
// speedup vs baseline: 1.4300x; 1.4300x over previous
#include <cuda_runtime.h>
#include <math.h>

#define Bn 16
#define Ln 2048
#define Dn 512
#define En 8
#define Hn 8
#define HDn 64
#define EHn 64
#define Fn 2048

typedef unsigned long long ull;
typedef unsigned int u32;

// -------- scratch --------
__device__ float g_gates[Bn*En];
__device__ float g_xn[Bn*Dn];
__device__ float g_qhp[4*En*Bn*Dn];        // k1 partials (split over reduction d)
__device__ float g_qk[Bn*EHn*Dn];
__device__ float g_scores[Bn*EHn*Ln];      // 8 MB, becomes probs in place
__device__ float g_ent[Bn*En];
__device__ float g_prp[4*Bn*EHn*Dn];       // k5 partials (split over L)
__device__ float g_attnp[4*En*Bn*Dn];      // k6a partials
__device__ float g_xp[4*En*Bn*Dn];         // k6b partials
__device__ float g_x[Bn*En*Dn];
__device__ float g_xo[Bn*En*Dn];
__device__ float g_h[Bn*En*Fn];
__device__ float g_y4[4*Bn*En*Dn];         // FFN2 f-split partials

__device__ __forceinline__ u32 tf32cvt(float x) {
    u32 r;
    asm("cvt.rna.tf32.f32 %0, %1;" : "=r"(r) : "f"(x));
    return r;
}

__device__ __forceinline__ void mma_tf32(float* c, const u32* a, const u32* b) {
    asm("mma.sync.aligned.m16n8k8.row.col.f32.tf32.tf32.f32 "
        "{%0,%1,%2,%3}, {%4,%5,%6,%7}, {%8,%9}, {%0,%1,%2,%3};"
        : "+f"(c[0]), "+f"(c[1]), "+f"(c[2]), "+f"(c[3])
        : "r"(a[0]), "r"(a[1]), "r"(a[2]), "r"(a[3]), "r"(b[0]), "r"(b[1]));
}

// K0: gating softmax + normalized query xn. grid=B, block=256
__global__ void k0_gate_ln(const float* __restrict__ query, const float* __restrict__ w_gate) {
    int b = blockIdx.x, t = threadIdx.x;
    __shared__ float q[Dn];
    __shared__ float red[256];
    __shared__ float lred[256*8];
    q[t] = query[b*Dn + t];
    q[t+256] = query[b*Dn + t + 256];
    __syncthreads();
    red[t] = q[t] + q[t+256];
    __syncthreads();
    for (int o = 128; o; o >>= 1) { if (t < o) red[t] += red[t+o]; __syncthreads(); }
    float mu = red[0] * (1.0f/Dn);
    __syncthreads();
    float d0 = q[t] - mu, d1 = q[t+256] - mu;
    red[t] = d0*d0 + d1*d1;
    __syncthreads();
    for (int o = 128; o; o >>= 1) { if (t < o) red[t] += red[t+o]; __syncthreads(); }
    float rstd = rsqrtf(red[0] * (1.0f/Dn) + 1e-5f);
    #pragma unroll
    for (int e = 0; e < 8; e++)
        lred[t*8+e] = q[t]*w_gate[t*8+e] + q[t+256]*w_gate[(t+256)*8+e];
    __syncthreads();
    for (int o = 128; o; o >>= 1) {
        if (t < o) {
            #pragma unroll
            for (int e = 0; e < 8; e++) lred[t*8+e] += lred[(t+o)*8+e];
        }
        __syncthreads();
    }
    if (t == 0) {
        float m = -1e30f;
        for (int e = 0; e < 8; e++) m = fmaxf(m, lred[e]);
        float s = 0.0f, ex[8];
        for (int e = 0; e < 8; e++) { ex[e] = expf(lred[e]-m); s += ex[e]; }
        for (int e = 0; e < 8; e++) g_gates[b*8+e] = ex[e]/s;
    }
    g_xn[b*Dn + t]       = d0*rstd;
    g_xn[b*Dn + t + 256] = d1*rstd;
}

// K1: qh partials, 2 outputs/thread. grid=(4 ktiles, E, 4 dsplit), block=256
__global__ void __launch_bounds__(256) k1_qh(const float* __restrict__ ln_q_g,
                      const float* __restrict__ ln_q_b,
                      const float* __restrict__ Wq) {
    int e = blockIdx.y, k0 = blockIdx.x*128, s = blockIdx.z;
    int t = threadIdx.x, g = t >> 6, lane = t & 63;
    __shared__ float qn[Bn*128];
    __shared__ float red[4*Bn*128];
    for (int i = t; i < Bn*128; i += 256) {
        int b = i >> 7, dd = i & 127;
        int d = s*128 + dd;
        qn[b*128+dd] = g_xn[b*Dn+d]*ln_q_g[e*Dn+d] + ln_q_b[e*Dn+d];
    }
    __syncthreads();
    float acc0[Bn], acc1[Bn];
    #pragma unroll
    for (int b = 0; b < Bn; b++) { acc0[b] = 0.0f; acc1[b] = 0.0f; }
    const float* W = Wq + (size_t)e*Dn*Dn + (size_t)(s*128 + g*32)*Dn + k0 + lane;
    #pragma unroll
    for (int d = 0; d < 32; d += 8) {
        float w0[8], w1[8];
        #pragma unroll
        for (int j = 0; j < 8; j++) {
            w0[j] = W[(size_t)(d+j)*Dn];
            w1[j] = W[(size_t)(d+j)*Dn + 64];
        }
        #pragma unroll
        for (int b = 0; b < Bn; b++) {
            float4 p0 = *(const float4*)&qn[b*128 + g*32 + d];
            float4 p1 = *(const float4*)&qn[b*128 + g*32 + d + 4];
            acc0[b] = fmaf(p0.x, w0[0], acc0[b]); acc1[b] = fmaf(p0.x, w1[0], acc1[b]);
            acc0[b] = fmaf(p0.y, w0[1], acc0[b]); acc1[b] = fmaf(p0.y, w1[1], acc1[b]);
            acc0[b] = fmaf(p0.z, w0[2], acc0[b]); acc1[b] = fmaf(p0.z, w1[2], acc1[b]);
            acc0[b] = fmaf(p0.w, w0[3], acc0[b]); acc1[b] = fmaf(p0.w, w1[3], acc1[b]);
            acc0[b] = fmaf(p1.x, w0[4], acc0[b]); acc1[b] = fmaf(p1.x, w1[4], acc1[b]);
            acc0[b] = fmaf(p1.y, w0[5], acc0[b]); acc1[b] = fmaf(p1.y, w1[5], acc1[b]);
            acc0[b] = fmaf(p1.z, w0[6], acc0[b]); acc1[b] = fmaf(p1.z, w1[6], acc1[b]);
            acc0[b] = fmaf(p1.w, w0[7], acc0[b]); acc1[b] = fmaf(p1.w, w1[7], acc1[b]);
        }
    }
    __syncthreads();
    #pragma unroll
    for (int b = 0; b < Bn; b++) {
        red[(g*Bn + b)*128 + lane]      = acc0[b];
        red[(g*Bn + b)*128 + lane + 64] = acc1[b];
    }
    __syncthreads();
    for (int i = t; i < Bn*128; i += 256) {
        int b = i >> 7, kk = i & 127;
        float v = red[(0*Bn+b)*128+kk]+red[(1*Bn+b)*128+kk]+red[(2*Bn+b)*128+kk]+red[(3*Bn+b)*128+kk];
        g_qhp[(((size_t)s*En + e)*Bn + b)*Dn + k0 + kk] = v;
    }
}

// K2: qk[b,eh,d] = (sum partials + bq) . Wk row slices, scaled. grid=(EH, 2), block=256
__global__ void __launch_bounds__(256) k2_qk(const float* __restrict__ Wk,
                                             const float* __restrict__ bq) {
    int eh = blockIdx.x, dc = blockIdx.y;
    int e = eh >> 3, h = eh & 7;
    int t = threadIdx.x;
    int d = dc*256 + t;
    __shared__ float qs[Bn][HDn];
    for (int i = t; i < Bn*HDn; i += 256) {
        int b = i >> 6, c = i & 63;
        float v = bq[e*Dn + h*HDn + c];
        #pragma unroll
        for (int s = 0; s < 4; s++)
            v += g_qhp[(((size_t)s*En + e)*Bn + b)*Dn + h*HDn + c];
        qs[b][c] = v;
    }
    __syncthreads();
    const float4* W4 = (const float4*)(Wk + (size_t)e*Dn*Dn + (size_t)d*Dn + h*HDn);
    float acc[Bn];
    #pragma unroll
    for (int b = 0; b < Bn; b++) acc[b] = 0.0f;
    #pragma unroll
    for (int c4 = 0; c4 < 16; c4++) {
        float4 w = W4[c4];
        int c = c4*4;
        #pragma unroll
        for (int b = 0; b < Bn; b++) {
            acc[b] = fmaf(qs[b][c],   w.x, acc[b]);
            acc[b] = fmaf(qs[b][c+1], w.y, acc[b]);
            acc[b] = fmaf(qs[b][c+2], w.z, acc[b]);
            acc[b] = fmaf(qs[b][c+3], w.w, acc[b]);
        }
    }
    #pragma unroll
    for (int b = 0; b < Bn; b++) g_qk[((size_t)b*EHn+eh)*Dn + d] = acc[b]*0.125f;
}

// K3: scores = R @ qk^T per b, via mma.sync tf32. Tile 128(l) x 64(eh), K=512.
// grid=(16 ltiles, B), 128 threads (4 warps). Warp w: l-range [w*32, w*32+32), all 64 eh.
__global__ void __launch_bounds__(128, 3) k3_scores(const float* __restrict__ R) {
    int b = blockIdx.y, l0 = blockIdx.x*128;
    int t = threadIdx.x, w = t >> 5, lane = t & 31;
    int gid = lane >> 2, tig = lane & 3;
    __shared__ u32 As[128][36];      // [l][k] tf32
    __shared__ u32 Bs[64][36];       // [eh][k] tf32
    float acc[2][8][4];
    #pragma unroll
    for (int i = 0; i < 2; i++)
        #pragma unroll
        for (int j = 0; j < 8; j++)
            #pragma unroll
            for (int r = 0; r < 4; r++) acc[i][j][r] = 0.0f;

    const float* Ar = R + ((size_t)b*Ln + l0 + t)*Dn;              // thread t stages row l0+t
    const float* Br = g_qk + ((size_t)b*EHn + (t>>1))*Dn + (t&1)*16;
    float4 areg[8], breg[4];
    #pragma unroll
    for (int j = 0; j < 8; j++) areg[j] = *(const float4*)(Ar + 4*j);
    #pragma unroll
    for (int j = 0; j < 4; j++) breg[j] = *(const float4*)(Br + 4*j);

    for (int s = 0; s < 16; s++) {
        __syncthreads();
        #pragma unroll
        for (int j = 0; j < 8; j++)
            *(uint4*)&As[t][4*j] = make_uint4(tf32cvt(areg[j].x), tf32cvt(areg[j].y),
                                              tf32cvt(areg[j].z), tf32cvt(areg[j].w));
        #pragma unroll
        for (int j = 0; j < 4; j++)
            *(uint4*)&Bs[t>>1][(t&1)*16 + 4*j] = make_uint4(tf32cvt(breg[j].x), tf32cvt(breg[j].y),
                                                            tf32cvt(breg[j].z), tf32cvt(breg[j].w));
        __syncthreads();
        if (s+1 < 16) {
            const float* An = Ar + (s+1)*32;
            const float* Bq = Br + (s+1)*32;
            #pragma unroll
            for (int j = 0; j < 8; j++) areg[j] = *(const float4*)(An + 4*j);
            #pragma unroll
            for (int j = 0; j < 4; j++) breg[j] = *(const float4*)(Bq + 4*j);
        }
        #pragma unroll
        for (int k8 = 0; k8 < 4; k8++) {
            int kb = k8*8;
            u32 a[2][4], bb[8][2];
            #pragma unroll
            for (int i = 0; i < 2; i++) {
                int rb = w*32 + i*16;
                a[i][0] = As[rb + gid][kb + tig];
                a[i][1] = As[rb + gid + 8][kb + tig];
                a[i][2] = As[rb + gid][kb + tig + 4];
                a[i][3] = As[rb + gid + 8][kb + tig + 4];
            }
            #pragma unroll
            for (int j = 0; j < 8; j++) {
                bb[j][0] = Bs[j*8 + gid][kb + tig];
                bb[j][1] = Bs[j*8 + gid][kb + tig + 4];
            }
            #pragma unroll
            for (int i = 0; i < 2; i++)
                #pragma unroll
                for (int j = 0; j < 8; j++) mma_tf32(acc[i][j], a[i], bb[j]);
        }
    }
    // Epilogue: c0:(gid, 2tig) c1:(gid, 2tig+1) c2:(gid+8, 2tig) c3:(gid+8, 2tig+1); row=l, col=eh
    #pragma unroll
    for (int i = 0; i < 2; i++) {
        int l = l0 + w*32 + i*16 + gid;
        #pragma unroll
        for (int j = 0; j < 8; j++) {
            int eh = j*8 + 2*tig;
            g_scores[((size_t)b*EHn + eh  )*Ln + l    ] = acc[i][j][0];
            g_scores[((size_t)b*EHn + eh+1)*Ln + l    ] = acc[i][j][1];
            g_scores[((size_t)b*EHn + eh  )*Ln + l + 8] = acc[i][j][2];
            g_scores[((size_t)b*EHn + eh+1)*Ln + l + 8] = acc[i][j][3];
        }
    }
}

// K4: softmax per (b,e,h) warp-per-head + entropy. grid=B*E, block=256
__global__ void __launch_bounds__(256) k4_softmax() {
    int be = blockIdx.x;
    int t = threadIdx.x, w = t >> 5, lane = t & 31;
    __shared__ float red[256];
    float* base = g_scores + (size_t)be*Hn*Ln;
    float* src = base + (size_t)w*Ln;
    float4 v[16];
    float m = -1e30f;
    #pragma unroll
    for (int i = 0; i < 16; i++) {
        v[i] = *(const float4*)&src[(i*32 + lane)*4];
        m = fmaxf(m, fmaxf(fmaxf(v[i].x, v[i].y), fmaxf(v[i].z, v[i].w)));
    }
    #pragma unroll
    for (int o = 16; o; o >>= 1) m = fmaxf(m, __shfl_xor_sync(0xffffffffu, m, o));
    float s = 0.0f;
    #pragma unroll
    for (int i = 0; i < 16; i++) {
        v[i].x = __expf(v[i].x - m); v[i].y = __expf(v[i].y - m);
        v[i].z = __expf(v[i].z - m); v[i].w = __expf(v[i].w - m);
        s += v[i].x + v[i].y + v[i].z + v[i].w;
    }
    #pragma unroll
    for (int o = 16; o; o >>= 1) s += __shfl_xor_sync(0xffffffffu, s, o);
    float inv = 1.0f/s;
    #pragma unroll
    for (int i = 0; i < 16; i++) {
        v[i].x *= inv; v[i].y *= inv; v[i].z *= inv; v[i].w *= inv;
        *(float4*)&src[(i*32 + lane)*4] = v[i];
    }
    __syncthreads();
    float lent = 0.0f;
    for (int i = t; i < Ln; i += 256) {
        float s8 = 0.0f;
        #pragma unroll
        for (int h = 0; h < 8; h++) s8 += base[h*Ln + i];
        float p = fmaxf(s8*0.125f, 1e-12f);
        lent -= p*__logf(p);
    }
    red[t] = lent; __syncthreads();
    for (int o = 128; o; o >>= 1) { if (t < o) red[t] += red[t+o]; __syncthreads(); }
    if (t == 0) g_ent[be] = red[0];
}

// K5: pr partial = probs-chunk @ R-chunk via mma.sync tf32. Tile 64(eh) x 128(d), K=512 chunk.
// grid=(4 dtiles, B, 4 ks), 128 threads. Warp w: d-range [w*32, w*32+32), all 64 eh.
__global__ void __launch_bounds__(128, 3) k5_pr(const float* __restrict__ R) {
    int b = blockIdx.y, d0 = blockIdx.x*128, ks = blockIdx.z;
    int t = threadIdx.x, w = t >> 5, lane = t & 31;
    int gid = lane >> 2, tig = lane & 3;
    __shared__ u32 As[64][36];       // [eh][l] tf32 (probs)
    __shared__ u32 Bs[128][36];      // [d][l] tf32 (R transposed)
    float acc[4][4][4];
    #pragma unroll
    for (int i = 0; i < 4; i++)
        #pragma unroll
        for (int j = 0; j < 4; j++)
            #pragma unroll
            for (int r = 0; r < 4; r++) acc[i][j][r] = 0.0f;

    // A stage: thread t -> eh=t/2, half=t&1 (16 floats)
    const float* Pr = g_scores + ((size_t)b*EHn + (t>>1))*Ln + ks*512 + (t&1)*16;
    // B stage: thread t -> l=lane, d-slice w*32.. (+32) (32 floats, transposed store)
    const float* Rr = R + ((size_t)b*Ln + ks*512 + lane)*Dn + d0 + w*32;
    float4 preg[4], rreg[8];
    #pragma unroll
    for (int j = 0; j < 4; j++) preg[j] = *(const float4*)(Pr + 4*j);
    #pragma unroll
    for (int j = 0; j < 8; j++) rreg[j] = *(const float4*)(Rr + 4*j);

    for (int s = 0; s < 16; s++) {
        __syncthreads();
        #pragma unroll
        for (int j = 0; j < 4; j++)
            *(uint4*)&As[t>>1][(t&1)*16 + 4*j] = make_uint4(tf32cvt(preg[j].x), tf32cvt(preg[j].y),
                                                            tf32cvt(preg[j].z), tf32cvt(preg[j].w));
        #pragma unroll
        for (int j = 0; j < 8; j++) {
            int db = w*32 + 4*j;
            Bs[db+0][lane] = tf32cvt(rreg[j].x);
            Bs[db+1][lane] = tf32cvt(rreg[j].y);
            Bs[db+2][lane] = tf32cvt(rreg[j].z);
            Bs[db+3][lane] = tf32cvt(rreg[j].w);
        }
        __syncthreads();
        if (s+1 < 16) {
            const float* Pn = Pr + (s+1)*32;
            const float* Rn = Rr + (size_t)(s+1)*32*Dn;
            #pragma unroll
            for (int j = 0; j < 4; j++) preg[j] = *(const float4*)(Pn + 4*j);
            #pragma unroll
            for (int j = 0; j < 8; j++) rreg[j] = *(const float4*)(Rn + 4*j);
        }
        #pragma unroll
        for (int k8 = 0; k8 < 4; k8++) {
            int kb = k8*8;
            u32 a[4][4], bb[4][2];
            #pragma unroll
            for (int i = 0; i < 4; i++) {
                int rb = i*16;
                a[i][0] = As[rb + gid][kb + tig];
                a[i][1] = As[rb + gid + 8][kb + tig];
                a[i][2] = As[rb + gid][kb + tig + 4];
                a[i][3] = As[rb + gid + 8][kb + tig + 4];
            }
            #pragma unroll
            for (int j = 0; j < 4; j++) {
                int nb = w*32 + j*8 + gid;
                bb[j][0] = Bs[nb][kb + tig];
                bb[j][1] = Bs[nb][kb + tig + 4];
            }
            #pragma unroll
            for (int i = 0; i < 4; i++)
                #pragma unroll
                for (int j = 0; j < 4; j++) mma_tf32(acc[i][j], a[i], bb[j]);
        }
    }
    // Epilogue: row=eh, col=d. c0/c1 at (gid, 2tig/2tig+1), c2/c3 at gid+8.
    #pragma unroll
    for (int i = 0; i < 4; i++) {
        int eh0 = i*16 + gid;
        #pragma unroll
        for (int j = 0; j < 4; j++) {
            int d = d0 + w*32 + j*8 + 2*tig;
            float* base0 = &g_prp[(((size_t)ks*Bn + b)*EHn + eh0)*Dn + d];
            float* base1 = &g_prp[(((size_t)ks*Bn + b)*EHn + eh0 + 8)*Dn + d];
            *(float2*)base0 = make_float2(acc[i][j][0], acc[i][j][1]);
            *(float2*)base1 = make_float2(acc[i][j][2], acc[i][j][3]);
        }
    }
}

// K6a: attn partials = pr @ Wv (split over d). grid=(EH, 4 s), block=256
__global__ void __launch_bounds__(256) k6a_attn(const float* __restrict__ Wv) {
    int eh = blockIdx.x, s = blockIdx.y;
    int e = eh >> 3, h = eh & 7;
    int t = threadIdx.x, g = t >> 5, lane = t & 31;
    __shared__ float ps[Bn*128];
    __shared__ float sred[8*Bn*64];
    for (int i = t; i < Bn*128; i += 256) {
        int b = i >> 7, dd = i & 127;
        float v = 0.0f;
        #pragma unroll
        for (int ks = 0; ks < 4; ks++)
            v += g_prp[(((size_t)ks*Bn + b)*EHn + eh)*Dn + s*128 + dd];
        ps[b*128+dd] = v;
    }
    __syncthreads();
    float acc0[Bn], acc1[Bn];
    #pragma unroll
    for (int b = 0; b < Bn; b++) { acc0[b] = 0.0f; acc1[b] = 0.0f; }
    const float* W = Wv + (size_t)e*Dn*Dn + (size_t)(s*128 + g*16)*Dn + h*HDn + lane;
    #pragma unroll
    for (int d = 0; d < 16; d += 8) {
        float w0[8], w1[8];
        #pragma unroll
        for (int j = 0; j < 8; j++) {
            w0[j] = W[(size_t)(d+j)*Dn];
            w1[j] = W[(size_t)(d+j)*Dn + 32];
        }
        #pragma unroll
        for (int b = 0; b < Bn; b++) {
            float4 q0 = *(const float4*)&ps[b*128 + g*16 + d];
            float4 q1 = *(const float4*)&ps[b*128 + g*16 + d + 4];
            acc0[b] = fmaf(q0.x, w0[0], acc0[b]); acc1[b] = fmaf(q0.x, w1[0], acc1[b]);
            acc0[b] = fmaf(q0.y, w0[1], acc0[b]); acc1[b] = fmaf(q0.y, w1[1], acc1[b]);
            acc0[b] = fmaf(q0.z, w0[2], acc0[b]); acc1[b] = fmaf(q0.z, w1[2], acc1[b]);
            acc0[b] = fmaf(q0.w, w0[3], acc0[b]); acc1[b] = fmaf(q0.w, w1[3], acc1[b]);
            acc0[b] = fmaf(q1.x, w0[4], acc0[b]); acc1[b] = fmaf(q1.x, w1[4], acc1[b]);
            acc0[b] = fmaf(q1.y, w0[5], acc0[b]); acc1[b] = fmaf(q1.y, w1[5], acc1[b]);
            acc0[b] = fmaf(q1.z, w0[6], acc0[b]); acc1[b] = fmaf(q1.z, w1[6], acc1[b]);
            acc0[b] = fmaf(q1.w, w0[7], acc0[b]); acc1[b] = fmaf(q1.w, w1[7], acc1[b]);
        }
    }
    __syncthreads();
    #pragma unroll
    for (int b = 0; b < Bn; b++) {
        sred[(g*Bn + b)*64 + lane]      = acc0[b];
        sred[(g*Bn + b)*64 + lane + 32] = acc1[b];
    }
    __syncthreads();
    for (int i = t; i < Bn*64; i += 256) {
        int b = i >> 6, cc = i & 63;
        float v = 0.0f;
        #pragma unroll
        for (int gg = 0; gg < 8; gg++) v += sred[(gg*Bn + b)*64 + cc];
        g_attnp[(((size_t)s*En + e)*Bn + b)*Dn + h*HDn + cc] = v;
    }
}

// K6b: x partials = attn @ Wo (split over d). grid=(4 ktiles, E, 4 s), block=256
__global__ void __launch_bounds__(256) k6b_attnout(const float* __restrict__ Wo,
                                                   const float* __restrict__ bv) {
    int e = blockIdx.y, k0 = blockIdx.x*128, s = blockIdx.z;
    int t = threadIdx.x, g = t >> 6, lane = t & 63;
    __shared__ float as_[Bn*128];
    __shared__ float red[4*Bn*128];
    for (int i = t; i < Bn*128; i += 256) {
        int b = i >> 7, dd = i & 127;
        int d = s*128 + dd;
        float v = bv[e*Dn + d];
        #pragma unroll
        for (int sp = 0; sp < 4; sp++)
            v += g_attnp[(((size_t)sp*En + e)*Bn + b)*Dn + d];
        as_[b*128+dd] = v;
    }
    __syncthreads();
    float acc0[Bn], acc1[Bn];
    #pragma unroll
    for (int b = 0; b < Bn; b++) { acc0[b] = 0.0f; acc1[b] = 0.0f; }
    const float* W = Wo + (size_t)e*Dn*Dn + (size_t)(s*128 + g*32)*Dn + k0 + lane;
    #pragma unroll
    for (int d = 0; d < 32; d += 8) {
        float w0[8], w1[8];
        #pragma unroll
        for (int j = 0; j < 8; j++) {
            w0[j] = W[(size_t)(d+j)*Dn];
            w1[j] = W[(size_t)(d+j)*Dn + 64];
        }
        #pragma unroll
        for (int b = 0; b < Bn; b++) {
            float4 q0 = *(const float4*)&as_[b*128 + g*32 + d];
            float4 q1 = *(const float4*)&as_[b*128 + g*32 + d + 4];
            acc0[b] = fmaf(q0.x, w0[0], acc0[b]); acc1[b] = fmaf(q0.x, w1[0], acc1[b]);
            acc0[b] = fmaf(q0.y, w0[1], acc0[b]); acc1[b] = fmaf(q0.y, w1[1], acc1[b]);
            acc0[b] = fmaf(q0.z, w0[2], acc0[b]); acc1[b] = fmaf(q0.z, w1[2], acc1[b]);
            acc0[b] = fmaf(q0.w, w0[3], acc0[b]); acc1[b] = fmaf(q0.w, w1[3], acc1[b]);
            acc0[b] = fmaf(q1.x, w0[4], acc0[b]); acc1[b] = fmaf(q1.x, w1[4], acc1[b]);
            acc0[b] = fmaf(q1.y, w0[5], acc0[b]); acc1[b] = fmaf(q1.y, w1[5], acc1[b]);
            acc0[b] = fmaf(q1.z, w0[6], acc0[b]); acc1[b] = fmaf(q1.z, w1[6], acc1[b]);
            acc0[b] = fmaf(q1.w, w0[7], acc0[b]); acc1[b] = fmaf(q1.w, w1[7], acc1[b]);
        }
    }
    __syncthreads();
    #pragma unroll
    for (int b = 0; b < Bn; b++) {
        red[(g*Bn + b)*128 + lane]      = acc0[b];
        red[(g*Bn + b)*128 + lane + 64] = acc1[b];
    }
    __syncthreads();
    for (int i = t; i < Bn*128; i += 256) {
        int b = i >> 7, kk = i & 127;
        float v = red[(0*Bn+b)*128+kk]+red[(1*Bn+b)*128+kk]+red[(2*Bn+b)*128+kk]+red[(3*Bn+b)*128+kk];
        g_xp[(((size_t)s*En + e)*Bn + b)*Dn + k0 + kk] = v;
    }
}

// K_ln2: x = query + bo + sum xp; write g_x and g_xo=LN(x). grid=B*E, block=256
__global__ void __launch_bounds__(256) k_ln2(const float* __restrict__ ln_o_g,
                      const float* __restrict__ ln_o_b,
                      const float* __restrict__ bo, const float* __restrict__ query) {
    int be = blockIdx.x, b = be >> 3, e = be & 7;
    int t = threadIdx.x;
    __shared__ float red[256];
    float v0 = query[b*Dn + t]     + bo[e*Dn + t];
    float v1 = query[b*Dn + t+256] + bo[e*Dn + t+256];
    #pragma unroll
    for (int s = 0; s < 4; s++) {
        v0 += g_xp[(((size_t)s*En + e)*Bn + b)*Dn + t];
        v1 += g_xp[(((size_t)s*En + e)*Bn + b)*Dn + t + 256];
    }
    g_x[be*Dn + t] = v0;
    g_x[be*Dn + t+256] = v1;
    red[t] = v0 + v1; __syncthreads();
    for (int o = 128; o; o >>= 1) { if (t < o) red[t] += red[t+o]; __syncthreads(); }
    float mu = red[0]*(1.0f/Dn); __syncthreads();
    float d0 = v0-mu, d1 = v1-mu;
    red[t] = d0*d0 + d1*d1; __syncthreads();
    for (int o = 128; o; o >>= 1) { if (t < o) red[t] += red[t+o]; __syncthreads(); }
    float rstd = rsqrtf(red[0]*(1.0f/Dn) + 1e-5f);
    g_xo[be*Dn + t]     = d0*rstd*ln_o_g[e*Dn+t]     + ln_o_b[e*Dn+t];
    g_xo[be*Dn + t+256] = d1*rstd*ln_o_g[e*Dn+t+256] + ln_o_b[e*Dn+t+256];
}

// K7: h = gelu(xo @ W1 + b1). 2 outputs/thread. grid=(16 ftiles, E), block=256
__global__ void __launch_bounds__(256) k7_ffn1(const float* __restrict__ W1,
                                               const float* __restrict__ b1) {
    int e = blockIdx.y, f0 = blockIdx.x*128;
    int t = threadIdx.x, g = t >> 6, lane = t & 63;
    __shared__ float xs[Bn*Dn];
    for (int i = t; i < Bn*Dn; i += 256) {
        int b = i >> 9, d = i & 511;
        xs[b*Dn+d] = g_xo[(b*En+e)*Dn + d];
    }
    __syncthreads();
    float acc0[Bn], acc1[Bn];
    #pragma unroll
    for (int b = 0; b < Bn; b++) { acc0[b] = 0.0f; acc1[b] = 0.0f; }
    const float* W = W1 + (size_t)e*Dn*Fn + (size_t)(g*128)*Fn + f0 + lane;
    #pragma unroll 2
    for (int d = 0; d < 128; d += 8) {
        float w0[8], w1[8];
        #pragma unroll
        for (int j = 0; j < 8; j++) {
            w0[j] = W[(size_t)(d+j)*Fn];
            w1[j] = W[(size_t)(d+j)*Fn + 64];
        }
        #pragma unroll
        for (int b = 0; b < Bn; b++) {
            float4 x0 = *(const float4*)&xs[b*Dn + g*128 + d];
            float4 x1 = *(const float4*)&xs[b*Dn + g*128 + d + 4];
            acc0[b] = fmaf(x0.x, w0[0], acc0[b]); acc1[b] = fmaf(x0.x, w1[0], acc1[b]);
            acc0[b] = fmaf(x0.y, w0[1], acc0[b]); acc1[b] = fmaf(x0.y, w1[1], acc1[b]);
            acc0[b] = fmaf(x0.z, w0[2], acc0[b]); acc1[b] = fmaf(x0.z, w1[2], acc1[b]);
            acc0[b] = fmaf(x0.w, w0[3], acc0[b]); acc1[b] = fmaf(x0.w, w1[3], acc1[b]);
            acc0[b] = fmaf(x1.x, w0[4], acc0[b]); acc1[b] = fmaf(x1.x, w1[4], acc1[b]);
            acc0[b] = fmaf(x1.y, w0[5], acc0[b]); acc1[b] = fmaf(x1.y, w1[5], acc1[b]);
            acc0[b] = fmaf(x1.z, w0[6], acc0[b]); acc1[b] = fmaf(x1.z, w1[6], acc1[b]);
            acc0[b] = fmaf(x1.w, w0[7], acc0[b]); acc1[b] = fmaf(x1.w, w1[7], acc1[b]);
        }
    }
    __syncthreads();
    float* red = xs;
    #pragma unroll
    for (int b = 0; b < Bn; b++) {
        red[(g*Bn + b)*128 + lane]      = acc0[b];
        red[(g*Bn + b)*128 + lane + 64] = acc1[b];
    }
    __syncthreads();
    for (int i = t; i < Bn*128; i += 256) {
        int b = i >> 7, ff = i & 127;
        float v = red[(0*Bn+b)*128+ff]+red[(1*Bn+b)*128+ff]+red[(2*Bn+b)*128+ff]+red[(3*Bn+b)*128+ff]
                + b1[e*Fn + f0+ff];
        v = 0.5f*v*(1.0f + erff(v*0.70710678118654752f));
        g_h[(b*En+e)*Fn + f0+ff] = v;
    }
}

// K8: y partials = h_chunk @ W2_chunk. 2 outputs/thread. grid=(4 ktiles, E, 4 fc), block=256
__global__ void __launch_bounds__(256) k8_ffn2(const float* __restrict__ W2) {
    int e = blockIdx.y, k0 = blockIdx.x*128, fc = blockIdx.z;
    int t = threadIdx.x, g = t >> 6, lane = t & 63;
    __shared__ float hs[Bn*512];
    for (int i = t; i < Bn*512; i += 256) {
        int b = i >> 9, f = i & 511;
        hs[b*512+f] = g_h[(b*En+e)*Fn + fc*512 + f];
    }
    __syncthreads();
    float acc0[Bn], acc1[Bn];
    #pragma unroll
    for (int b = 0; b < Bn; b++) { acc0[b] = 0.0f; acc1[b] = 0.0f; }
    const float* W = W2 + (size_t)e*Fn*Dn + ((size_t)fc*512 + g*128)*Dn + k0 + lane;
    #pragma unroll 2
    for (int ff = 0; ff < 128; ff += 8) {
        float w0[8], w1[8];
        #pragma unroll
        for (int j = 0; j < 8; j++) {
            w0[j] = W[(size_t)(ff+j)*Dn];
            w1[j] = W[(size_t)(ff+j)*Dn + 64];
        }
        #pragma unroll
        for (int b = 0; b < Bn; b++) {
            float4 h0 = *(const float4*)&hs[b*512 + g*128 + ff];
            float4 h1 = *(const float4*)&hs[b*512 + g*128 + ff + 4];
            acc0[b] = fmaf(h0.x, w0[0], acc0[b]); acc1[b] = fmaf(h0.x, w1[0], acc1[b]);
            acc0[b] = fmaf(h0.y, w0[1], acc0[b]); acc1[b] = fmaf(h0.y, w1[1], acc1[b]);
            acc0[b] = fmaf(h0.z, w0[2], acc0[b]); acc1[b] = fmaf(h0.z, w1[2], acc1[b]);
            acc0[b] = fmaf(h0.w, w0[3], acc0[b]); acc1[b] = fmaf(h0.w, w1[3], acc1[b]);
            acc0[b] = fmaf(h1.x, w0[4], acc0[b]); acc1[b] = fmaf(h1.x, w1[4], acc1[b]);
            acc0[b] = fmaf(h1.y, w0[5], acc0[b]); acc1[b] = fmaf(h1.y, w1[5], acc1[b]);
            acc0[b] = fmaf(h1.z, w0[6], acc0[b]); acc1[b] = fmaf(h1.z, w1[6], acc1[b]);
            acc0[b] = fmaf(h1.w, w0[7], acc0[b]); acc1[b] = fmaf(h1.w, w1[7], acc1[b]);
        }
    }
    __syncthreads();
    float* red = hs;
    #pragma unroll
    for (int b = 0; b < Bn; b++) {
        red[(g*Bn + b)*128 + lane]      = acc0[b];
        red[(g*Bn + b)*128 + lane + 64] = acc1[b];
    }
    __syncthreads();
    for (int i = t; i < Bn*128; i += 256) {
        int b = i >> 7, kk = i & 127;
        float v = red[(0*Bn+b)*128+kk]+red[(1*Bn+b)*128+kk]+red[(2*Bn+b)*128+kk]+red[(3*Bn+b)*128+kk];
        g_y4[(((size_t)fc*Bn + b)*En + e)*Dn + k0 + kk] = v;
    }
}

// K9: assemble y = x + b2 + sum partials; weights; mixture. grid=B, block=512
__global__ void __launch_bounds__(512) k9_final(float* __restrict__ out,
                                                const float* __restrict__ b2) {
    int b = blockIdx.x, t = threadIdx.x;
    __shared__ float gt[8];
    if (t < 8) gt[t] = g_gates[b*8+t]*__expf(-0.5f*g_ent[b*8+t]);
    __syncthreads();
    if (t == 0) {
        float s = 0.0f;
        for (int e = 0; e < 8; e++) s += gt[e];
        float inv = 1.0f/(s + 1e-9f);
        for (int e = 0; e < 8; e++) gt[e] *= inv;
    }
    __syncthreads();
    if (t < 8) out[Bn*Dn + Bn*En*Dn + b*8 + t] = gt[t];
    float m = 0.0f;
    #pragma unroll
    for (int e = 0; e < 8; e++) {
        float y = g_x[(b*En+e)*Dn + t] + b2[e*Dn + t];
        #pragma unroll
        for (int fc = 0; fc < 4; fc++)
            y += g_y4[(((size_t)fc*Bn + b)*En + e)*Dn + t];
        out[Bn*Dn + (b*En+e)*Dn + t] = y;
        m = fmaf(gt[e], y, m);
    }
    out[b*Dn + t] = m;   // ALPHA=1 -> fused = mixture
}

extern "C" void kernel_launch(void* const* d_in, const int* in_sizes, int n_in,
                              void* d_out, int out_size) {
    const float* query     = (const float*)d_in[0];
    const float* retrieved = (const float*)d_in[1];
    const float* w_gate    = (const float*)d_in[2];
    const float* ln_q_g    = (const float*)d_in[3];
    const float* ln_q_b    = (const float*)d_in[4];
    const float* Wq        = (const float*)d_in[5];
    const float* bq        = (const float*)d_in[6];
    const float* Wk        = (const float*)d_in[7];
    /* d_in[8] = bk cancels in softmax */
    const float* Wv        = (const float*)d_in[9];
    const float* bv        = (const float*)d_in[10];
    const float* Wo        = (const float*)d_in[11];
    const float* bo        = (const float*)d_in[12];
    const float* ln_o_g    = (const float*)d_in[13];
    const float* ln_o_b    = (const float*)d_in[14];
    const float* W1        = (const float*)d_in[15];
    const float* b1        = (const float*)d_in[16];
    const float* W2        = (const float*)d_in[17];
    const float* b2        = (const float*)d_in[18];
    float* out = (float*)d_out;

    k0_gate_ln<<<Bn, 256>>>(query, w_gate);
    k1_qh<<<dim3(4, En, 4), 256>>>(ln_q_g, ln_q_b, Wq);
    k2_qk<<<dim3(EHn, 2), 256>>>(Wk, bq);
    k3_scores<<<dim3(16, Bn), 128>>>(retrieved);
    k4_softmax<<<Bn*En, 256>>>();
    k5_pr<<<dim3(4, Bn, 4), 128>>>(retrieved);
    k6a_attn<<<dim3(EHn, 4), 256>>>(Wv);
    k6b_attnout<<<dim3(4, En, 4), 256>>>(Wo, bv);
    k_ln2<<<Bn*En, 256>>>(ln_o_g, ln_o_b, bo, query);
    k7_ffn1<<<dim3(16, En), 256>>>(W1, b1);
    k8_ffn2<<<dim3(4, En, 4), 256>>>(W2);
    k9_final<<<Bn, 512>>>(out, b2);
}